// round 8
// baseline (speedup 1.0000x reference)
#include <cuda_runtime.h>
#include <cuda_bf16.h>
#include <math.h>

#define NB 512
#define NT 20
#define NOBJ 36
#define ND 2048
#define NEMB 300
#define NE 512
#define NHM 1024
#define NHO 256

constexpr int BT  = NB * NT;          // 10240
constexpr int KAM = 832;
constexpr int KAO = 1344;
constexpr int GM4 = 4 * NHM;          // 4096
constexpr int GO4 = 4 * NHO;          // 1024
constexpr int LDW_M = NE + NEMB + ND;       // 2860
constexpr int LDW_O = 2 * NE + NEMB + ND;   // 3372
constexpr int KIN_M = NE + NEMB;            // 812
constexpr int KIN_O = 2 * NE + NEMB;        // 1324

// ---------------- scratch arena ----------------
constexpr size_t OFF_MEANB = 0;                                      // bf16 NB*ND
constexpr size_t OFF_AM    = OFF_MEANB + (size_t)NB * ND / 2;
constexpr size_t OFF_AO    = OFF_AM    + (size_t)BT * KAM / 2;
constexpr size_t OFF_GM    = OFF_AO    + (size_t)BT * KAO / 2;       // f32
constexpr size_t OFF_GO    = OFF_GM    + (size_t)BT * GM4;
constexpr size_t OFF_FM    = OFF_GO    + (size_t)BT * GO4;
constexpr size_t OFF_FO    = OFF_FM    + (size_t)NB * GM4;
constexpr size_t OFF_HMA   = OFF_FO    + (size_t)NB * GO4;           // bf16
constexpr size_t OFF_HMB   = OFF_HMA   + (size_t)NB * NHM / 2;
constexpr size_t OFF_CM    = OFF_HMB   + (size_t)NB * NHM / 2;       // f32
constexpr size_t OFF_HOA   = OFF_CM    + (size_t)NB * NHM;
constexpr size_t OFF_HOB   = OFF_HOA   + (size_t)NB * NHO / 2;
constexpr size_t OFF_CO    = OFF_HOB   + (size_t)NB * NHO / 2;
constexpr size_t OFF_HMS   = OFF_CO    + (size_t)NB * NHO;           // bf16
constexpr size_t OFF_HOS   = OFF_HMS   + (size_t)BT * NHM / 2;
constexpr size_t OFF_OUTM  = OFF_HOS   + (size_t)BT * NHO / 2;       // f32
constexpr size_t OFF_OUTO  = OFF_OUTM  + (size_t)BT * 2 * NE;
constexpr size_t OFF_WIMIN = OFF_OUTO  + (size_t)BT * 2 * NE;        // bf16
constexpr size_t OFF_WIMFT = OFF_WIMIN + (size_t)GM4 * KAM / 2;
constexpr size_t OFF_WIOIN = OFF_WIMFT + (size_t)GM4 * ND / 2;
constexpr size_t OFF_WIOFT = OFF_WIOIN + (size_t)GO4 * KAO / 2;
constexpr size_t OFF_WHM   = OFF_WIOFT + (size_t)GO4 * ND / 2;
constexpr size_t OFF_WHO   = OFF_WHM   + (size_t)GM4 * NHM / 2;
constexpr size_t OFF_FCM   = OFF_WHO   + (size_t)GO4 * NHO / 2;
constexpr size_t OFF_FCO   = OFF_FCM   + (size_t)1024 * NHM / 2;
constexpr size_t OFF_BM    = OFF_FCO   + (size_t)1024 * NHO / 2;     // f32
constexpr size_t OFF_BO    = OFF_BM    + GM4;
constexpr size_t TOTAL     = OFF_BO    + GO4;

__device__ float d_scratch[TOTAL];

typedef __nv_bfloat16 bf16;

#define ABLK 40

__device__ __forceinline__ void mma_bf16(float* d, const unsigned* a, const unsigned* b) {
    asm volatile(
        "mma.sync.aligned.m16n8k16.row.col.f32.bf16.bf16.f32 "
        "{%0,%1,%2,%3},{%4,%5,%6,%7},{%8,%9},{%0,%1,%2,%3};"
        : "+f"(d[0]), "+f"(d[1]), "+f"(d[2]), "+f"(d[3])
        : "r"(a[0]), "r"(a[1]), "r"(a[2]), "r"(a[3]), "r"(b[0]), "r"(b[1]));
}

// =====================================================================
// WIDE GEMM: block 128(M) x 256(N), k-tile 32, 8 warps of 64x64.
// C[M,N] = A[M,K] @ W[N,K]^T (+bias). Double buffered (61.4KB dyn smem).
// =====================================================================
struct __align__(16) SmemBufW {
    unsigned A[4][8 * 2 * ABLK];    // 2560 u32
    unsigned B[2][32 * 2 * ABLK];   // 5120 u32
};
#define DYN_G (2 * (int)sizeof(SmemBufW))   // 61440

__device__ __forceinline__ void fill_wide(SmemBufW* buf, int tid,
                                          const uint4* av, const uint4* bv)
{
#pragma unroll
    for (int q = 0; q < 2; q++) {
        int v = tid + q * 256;
        int r = v >> 2, f8 = v & 3;
        int reg = ((r >> 3) & 1) + 2 * (f8 & 1);
        int off = ((r >> 4) * 2 + (f8 >> 1)) * ABLK + 4 * (r & 7);
        *(uint4*)&buf->A[reg][off] = av[q];
    }
#pragma unroll
    for (int q = 0; q < 4; q++) {
        int v = tid + q * 256;
        int r = v >> 2, f8 = v & 3;
        int reg = f8 & 1;
        int off = ((r >> 3) * 2 + (f8 >> 1)) * ABLK + 4 * (r & 7);
        *(uint4*)&buf->B[reg][off] = bv[q];
    }
}

__global__ __launch_bounds__(256, 1) void gemm_wide(
    const bf16* __restrict__ A, int lda,
    const bf16* __restrict__ W, int ldw,
    float* __restrict__ C, int ldc, int K,
    const float* __restrict__ bias)
{
    extern __shared__ SmemBufW sm[];   // sm[2]
    const int tid = threadIdx.x;
    const int lane = tid & 31;
    const int w = tid >> 5, wm = w & 1, wn = w >> 1;
    const long bm = (long)blockIdx.y * 128;
    const long bn = (long)blockIdx.x * 256;

    const bf16* Ab = A + bm * (size_t)lda;
    const bf16* Wb = W + bn * (size_t)ldw;

    float acc[4][8][4];
#pragma unroll
    for (int i = 0; i < 4; i++)
#pragma unroll
        for (int j = 0; j < 8; j++)
#pragma unroll
            for (int r = 0; r < 4; r++) acc[i][j][r] = 0.f;

    uint4 av[2], bv[4];
#pragma unroll
    for (int q = 0; q < 2; q++) {
        int v = tid + q * 256;
        int r = v >> 2, f8 = v & 3;
        av[q] = *(const uint4*)(Ab + (size_t)r * lda + 8 * f8);
    }
#pragma unroll
    for (int q = 0; q < 4; q++) {
        int v = tid + q * 256;
        int r = v >> 2, f8 = v & 3;
        bv[q] = *(const uint4*)(Wb + (size_t)r * ldw + 8 * f8);
    }
    fill_wide(&sm[0], tid, av, bv);
    __syncthreads();

    const int KT = K / 32;
    for (int kt = 0; kt < KT; kt++) {
        SmemBufW* b = &sm[kt & 1];
        const bool more = (kt + 1 < KT);
        if (more) {
            int k0 = (kt + 1) * 32;
#pragma unroll
            for (int q = 0; q < 2; q++) {
                int v = tid + q * 256;
                int r = v >> 2, f8 = v & 3;
                av[q] = *(const uint4*)(Ab + (size_t)r * lda + k0 + 8 * f8);
            }
#pragma unroll
            for (int q = 0; q < 4; q++) {
                int v = tid + q * 256;
                int r = v >> 2, f8 = v & 3;
                bv[q] = *(const uint4*)(Wb + (size_t)r * ldw + k0 + 8 * f8);
            }
        }

#pragma unroll
        for (int ik = 0; ik < 2; ik++) {
            unsigned af[4][4], bfr[8][2];
#pragma unroll
            for (int il = 0; il < 4; il++) {
                int off = ((wm * 4 + il) * 2 + ik) * ABLK + lane;
                af[il][0] = b->A[0][off];
                af[il][1] = b->A[1][off];
                af[il][2] = b->A[2][off];
                af[il][3] = b->A[3][off];
            }
#pragma unroll
            for (int jl = 0; jl < 8; jl++) {
                int off = ((wn * 8 + jl) * 2 + ik) * ABLK + lane;
                bfr[jl][0] = b->B[0][off];
                bfr[jl][1] = b->B[1][off];
            }
#pragma unroll
            for (int il = 0; il < 4; il++)
#pragma unroll
                for (int jl = 0; jl < 8; jl++)
                    mma_bf16(acc[il][jl], af[il], bfr[jl]);
        }

        if (more) {
            fill_wide(&sm[(kt + 1) & 1], tid, av, bv);
            __syncthreads();
        }
    }

    const int g = lane >> 2;
    const int cp = (lane & 3) * 2;
#pragma unroll
    for (int jl = 0; jl < 8; jl++) {
        long col = bn + wn * 64 + jl * 8 + cp;
        float b0 = 0.f, b1 = 0.f;
        if (bias) { b0 = bias[col]; b1 = bias[col + 1]; }
#pragma unroll
        for (int il = 0; il < 4; il++) {
            long row = bm + wm * 64 + il * 16 + g;
            *(float2*)(C + row * (long)ldc + col) =
                make_float2(acc[il][jl][0] + b0, acc[il][jl][1] + b1);
            *(float2*)(C + (row + 8) * (long)ldc + col) =
                make_float2(acc[il][jl][2] + b0, acc[il][jl][3] + b1);
        }
    }
}

// =====================================================================
// bf16 HMMA 128x128 core (R6, proven) — used by the fused LSTM step
// =====================================================================
struct __align__(16) SmemBuf {
    unsigned A[4][8 * 2 * ABLK];
    unsigned B[2][16 * 2 * ABLK];
};

__device__ __forceinline__ void fill_tiles(SmemBuf* buf, int tid,
                                           const uint4* av, const uint4* bv)
{
#pragma unroll
    for (int q = 0; q < 2; q++) {
        int v = tid + q * 256;
        int r = v >> 2, f8 = v & 3;
        {
            int reg = ((r >> 3) & 1) + 2 * (f8 & 1);
            int off = ((r >> 4) * 2 + (f8 >> 1)) * ABLK + 4 * (r & 7);
            *(uint4*)&buf->A[reg][off] = av[q];
        }
        {
            int reg = f8 & 1;
            int off = ((r >> 3) * 2 + (f8 >> 1)) * ABLK + 4 * (r & 7);
            *(uint4*)&buf->B[reg][off] = bv[q];
        }
    }
}

__device__ __forceinline__ void gemm_core_bf16(
    const bf16* __restrict__ A, int lda,
    const bf16* __restrict__ W, int ldw, int K,
    SmemBuf* sm, int tid, float acc[4][4][4])
{
    const int lane = tid & 31;
    const int w = tid >> 5, wm = w & 1, wn = w >> 1;

#pragma unroll
    for (int i = 0; i < 4; i++)
#pragma unroll
        for (int j = 0; j < 4; j++)
#pragma unroll
            for (int r = 0; r < 4; r++) acc[i][j][r] = 0.f;

    uint4 av[2], bv[2];
#pragma unroll
    for (int q = 0; q < 2; q++) {
        int v = tid + q * 256;
        int r = v >> 2, f8 = v & 3;
        av[q] = *(const uint4*)(A + (size_t)r * lda + 8 * f8);
        bv[q] = *(const uint4*)(W + (size_t)r * ldw + 8 * f8);
    }
    fill_tiles(&sm[0], tid, av, bv);
    __syncthreads();

    const int KT = K / 32;
    for (int kt = 0; kt < KT; kt++) {
        SmemBuf* b = &sm[kt & 1];
        const bool more = (kt + 1 < KT);
        if (more) {
            int k0 = (kt + 1) * 32;
#pragma unroll
            for (int q = 0; q < 2; q++) {
                int v = tid + q * 256;
                int r = v >> 2, f8 = v & 3;
                av[q] = *(const uint4*)(A + (size_t)r * lda + k0 + 8 * f8);
                bv[q] = *(const uint4*)(W + (size_t)r * ldw + k0 + 8 * f8);
            }
        }

#pragma unroll
        for (int ik = 0; ik < 2; ik++) {
            unsigned af[4][4], bfr[4][2];
#pragma unroll
            for (int il = 0; il < 4; il++) {
                int off = ((wm * 4 + il) * 2 + ik) * ABLK + lane;
                af[il][0] = b->A[0][off];
                af[il][1] = b->A[1][off];
                af[il][2] = b->A[2][off];
                af[il][3] = b->A[3][off];
            }
#pragma unroll
            for (int jl = 0; jl < 4; jl++) {
                int off = ((wn * 4 + jl) * 2 + ik) * ABLK + lane;
                bfr[jl][0] = b->B[0][off];
                bfr[jl][1] = b->B[1][off];
            }
#pragma unroll
            for (int il = 0; il < 4; il++)
#pragma unroll
                for (int jl = 0; jl < 4; jl++)
                    mma_bf16(acc[il][jl], af[il], bfr[jl]);
        }

        if (more) {
            fill_tiles(&sm[(kt + 1) & 1], tid, av, bv);
            __syncthreads();
        }
    }
}

// ---------------- fused LSTM step ----------------
__device__ __forceinline__ float tfast(float x) {
    float y;
    asm("tanh.approx.f32 %0, %1;" : "=f"(y) : "f"(x));
    return y;
}
__device__ __forceinline__ float sigf(float x) { return 0.5f * tfast(0.5f * x) + 0.5f; }

// G (per b,t) + F (per b, bias folded) read here; shfl gate exchange.
__device__ __forceinline__ void cell_epi(
    float acc[4][4][4], int tid,
    const float* __restrict__ G, const float* __restrict__ F,
    float* __restrict__ c,
    bf16* __restrict__ hout, bf16* __restrict__ Hseq,
    long bm, int bx, int H, int t)
{
    const int lane = tid & 31;
    const int w = tid >> 5, wm = w & 1, wn = w >> 1;
    const int g = lane >> 2;
    const bool odd = lane & 1;
    const int H4 = 4 * H;

#pragma unroll
    for (int il = 0; il < 4; il++) {
        long row = bm + wm * 64 + il * 16 + g + (odd ? 8 : 0);
#pragma unroll
        for (int jl = 0; jl < 4; jl++) {
            float s0 = odd ? acc[il][jl][0] : acc[il][jl][2];
            float s1 = odd ? acc[il][jl][1] : acc[il][jl][3];
            float r0 = __shfl_xor_sync(0xffffffffu, s0, 1);
            float r1 = __shfl_xor_sync(0xffffffffu, s1, 1);
            float gi, gf, gg, go;
            if (!odd) { gi = acc[il][jl][0]; gf = acc[il][jl][1]; gg = r0; go = r1; }
            else      { gi = r0; gf = r1; gg = acc[il][jl][2]; go = acc[il][jl][3]; }

            int ul = wn * 8 + jl * 2 + ((lane & 2) >> 1);
            size_t goff = (size_t)bx * 128 + ul * 4;
            const float4 G4 = *(const float4*)&G[(row * NT + t) * (size_t)H4 + goff];
            const float4 F4 = *(const float4*)&F[row * (size_t)H4 + goff];
            gi += G4.x + F4.x; gf += G4.y + F4.y;
            gg += G4.z + F4.z; go += G4.w + F4.w;

            int u = bx * 32 + ul;
            size_t si = (size_t)row * H + u;
            float cn = sigf(gf) * c[si] + sigf(gi) * tfast(gg);
            float hn = sigf(go) * tfast(cn);
            c[si] = cn;
            bf16 hb = __float2bfloat16(hn);
            hout[si] = hb;
            Hseq[(row * NT + t) * (size_t)H + u] = hb;
        }
    }
}

__global__ __launch_bounds__(256, 2) void lstm_step(
    const bf16* __restrict__ hmi, bf16* __restrict__ hmo, float* __restrict__ cm,
    const bf16* __restrict__ Whm, const float* __restrict__ Gm,
    const float* __restrict__ Fm, bf16* __restrict__ Hms,
    const bf16* __restrict__ hoi, bf16* __restrict__ hoo, float* __restrict__ co,
    const bf16* __restrict__ Who, const float* __restrict__ Go,
    const float* __restrict__ Fo, bf16* __restrict__ Hos,
    int t)
{
    __shared__ SmemBuf sm[2];
    const int tid = threadIdx.x;
    const int id = blockIdx.x;
    float acc[4][4][4];

    if (id < 128) {
        int bx = id & 31;
        long bm = (long)(id >> 5) * 128;
        gemm_core_bf16(hmi + bm * NHM, NHM, Whm + (size_t)bx * 128 * NHM, NHM,
                       NHM, sm, tid, acc);
        cell_epi(acc, tid, Gm, Fm, cm, hmo, Hms, bm, bx, NHM, t);
    } else {
        int r = id - 128;
        int bx = r & 7;
        long bm = (long)(r >> 3) * 128;
        gemm_core_bf16(hoi + bm * NHO, NHO, Who + (size_t)bx * 128 * NHO, NHO,
                       NHO, sm, tid, acc);
        cell_epi(acc, tid, Go, Fo, co, hoo, Hos, bm, bx, NHO, t);
    }
}

// ---------------- setup kernels ----------------
__global__ void objmean_kernel(const float* __restrict__ obj, bf16* __restrict__ meanb)
{
    int b = blockIdx.x;
    int tid = threadIdx.x;
    int w = tid >> 5, lane = tid & 31;
    __shared__ float mk[NOBJ];

    for (int n = w; n < NOBJ; n += 8) {
        const float* p = obj + ((size_t)b * NOBJ + n) * ND;
        float s = 0.f;
        for (int d = lane; d < ND; d += 32) s += fabsf(p[d]);
        for (int o = 16; o; o >>= 1) s += __shfl_down_sync(0xffffffffu, s, o);
        if (lane == 0) mk[n] = s > 0.f ? 1.f : 0.f;
    }
    __syncthreads();
    float cnt = 0.f;
#pragma unroll
    for (int n = 0; n < NOBJ; n++) cnt += mk[n];
    float inv = 1.f / fmaxf(cnt, 1e-9f);

    const float* ob = obj + (size_t)b * NOBJ * ND;
    for (int d = tid; d < ND; d += 256) {
        float acc = 0.f;
#pragma unroll 4
        for (int n = 0; n < NOBJ; n++) acc += ob[(size_t)n * ND + d] * mk[n];
        meanb[(size_t)b * ND + d] = __float2bfloat16(acc * inv);
    }
}

__global__ void build_Am(const float* __restrict__ qzm, const int* __restrict__ x,
                         const float* __restrict__ emb, bf16* __restrict__ Am)
{
    int r = blockIdx.x;
    int t = r % NT, b = r / NT;
    bf16* out = Am + (size_t)r * KAM;
    const float* z = qzm + ((size_t)b * NT + (t - 1)) * NE;
    const float* e = emb + (size_t)x[r] * NEMB;
    for (int c = threadIdx.x; c < KAM; c += blockDim.x) {
        float v;
        if (c < NE)              v = (t == 0) ? 0.f : z[c];
        else if (c < NE + NEMB)  v = e[c - NE];
        else                     v = 0.f;
        out[c] = __float2bfloat16(v);
    }
}

__global__ void build_Ao(const float* __restrict__ qzm, const float* __restrict__ qzo,
                         const int* __restrict__ x, const float* __restrict__ emb,
                         bf16* __restrict__ Ao)
{
    int r = blockIdx.x;
    int t = r % NT, b = r / NT;
    bf16* out = Ao + (size_t)r * KAO;
    const float* zc = qzm + ((size_t)b * NT + t) * NE;
    const float* zp = qzo + ((size_t)b * NT + (t - 1)) * NE;
    const float* e  = emb + (size_t)x[r] * NEMB;
    for (int c = threadIdx.x; c < KAO; c += blockDim.x) {
        float v;
        if (c < NE)                 v = zc[c];
        else if (c < 2 * NE)        v = (t == 0) ? 0.f : zp[c - NE];
        else if (c < 2 * NE + NEMB) v = e[c - 2 * NE];
        else                        v = 0.f;
        out[c] = __float2bfloat16(v);
    }
}

__global__ void reorder_ih(const float* __restrict__ src, int ldsrc, int kin,
                           bf16* __restrict__ din, int ldin,
                           bf16* __restrict__ dft, int H)
{
    int r = blockIdx.x;
    int u = r >> 2, g = r & 3;
    const float* s = src + (size_t)(g * H + u) * ldsrc;
    bf16* a = din + (size_t)r * ldin;
    bf16* b = dft + (size_t)r * ND;
    for (int c = threadIdx.x; c < ldin; c += blockDim.x)
        a[c] = __float2bfloat16(c < kin ? s[c] : 0.f);
    for (int c = threadIdx.x; c < ND; c += blockDim.x)
        b[c] = __float2bfloat16(s[kin + c]);
}

__global__ void reorder_hh(const float* __restrict__ src, bf16* __restrict__ dst, int H)
{
    int r = blockIdx.x;
    int u = r >> 2, g = r & 3;
    const float* s = src + (size_t)(g * H + u) * H;
    bf16* d = dst + (size_t)r * H;
    for (int c = threadIdx.x; c < H; c += blockDim.x)
        d[c] = __float2bfloat16(s[c]);
}

__global__ void reorder_bias(const float* __restrict__ src, float* __restrict__ dst, int H)
{
    int r = blockIdx.x * blockDim.x + threadIdx.x;
    if (r < 4 * H) { int u = r >> 2, g = r & 3; dst[r] = src[g * H + u]; }
}

__global__ void f2bf_kernel(const float* __restrict__ s, bf16* __restrict__ d, int n)
{
    int i = blockIdx.x * blockDim.x + threadIdx.x;
    if (i < n) d[i] = __float2bfloat16(s[i]);
}

__global__ void zero_state(bf16* hm, float* cm, bf16* ho, float* co)
{
    int idx = blockIdx.x * blockDim.x + threadIdx.x;
    if (idx < NB * NHM) { hm[idx] = __float2bfloat16(0.f); cm[idx] = 0.f; }
    if (idx < NB * NHO) { ho[idx] = __float2bfloat16(0.f); co[idx] = 0.f; }
}

__global__ void kl_kernel(const float* __restrict__ outm, const float* __restrict__ outo,
                          const float* __restrict__ qmm, const float* __restrict__ qlm,
                          const float* __restrict__ qmo, const float* __restrict__ qlo,
                          const int* __restrict__ x, float* __restrict__ out)
{
    int b = blockIdx.x;
    float acc = 0.f;
    for (int i = threadIdx.x; i < NT * NE; i += blockDim.x) {
        int t = i / NE;
        int e = i - t * NE;
        int tok = x[b * NT + t];
        if (tok == 0 || tok == 2) continue;
        size_t ro = (size_t)b * NT + t;
        size_t po = ro * (2 * NE);
        size_t qo = ro * NE + e;
        float pm = outm[po + e], pl = outm[po + NE + e];
        float qm = qmm[qo],      ql = qlm[qo];
        float dm = qm - pm;
        acc += 0.5f * (pl - ql) + (expf(ql) + dm * dm) / (2.f * expf(pl)) - 0.5f;
        pm = outo[po + e]; pl = outo[po + NE + e];
        qm = qmo[qo];      ql = qlo[qo];
        dm = qm - pm;
        acc += 0.5f * (pl - ql) + (expf(ql) + dm * dm) / (2.f * expf(pl)) - 0.5f;
    }
    __shared__ float sm[256];
    sm[threadIdx.x] = acc;
    __syncthreads();
    for (int s = 128; s; s >>= 1) {
        if (threadIdx.x < s) sm[threadIdx.x] += sm[threadIdx.x + s];
        __syncthreads();
    }
    if (threadIdx.x == 0) out[b] = sm[0];
}

// ---------------- host ----------------
extern "C" void kernel_launch(void* const* d_in, const int* in_sizes, int n_in,
                              void* d_out, int out_size)
{
    const float* obj_enc = (const float*)d_in[0];
    const int*   x       = (const int*)  d_in[1];
    const float* qmm     = (const float*)d_in[2];
    const float* qlm     = (const float*)d_in[3];
    const float* qzm     = (const float*)d_in[4];
    const float* qmo     = (const float*)d_in[5];
    const float* qlo     = (const float*)d_in[6];
    const float* qzo     = (const float*)d_in[7];
    const float* emd_W   = (const float*)d_in[8];
    const float* W_ih_m  = (const float*)d_in[9];
    const float* W_hh_m  = (const float*)d_in[10];
    const float* b_m     = (const float*)d_in[11];
    const float* W_ih_o  = (const float*)d_in[12];
    const float* W_hh_o  = (const float*)d_in[13];
    const float* b_o     = (const float*)d_in[14];
    const float* fc_m_W  = (const float*)d_in[15];
    const float* fc_m_b  = (const float*)d_in[16];
    const float* fc_o_W  = (const float*)d_in[17];
    const float* fc_o_b  = (const float*)d_in[18];
    float* out = (float*)d_out;

    float* s = nullptr;
    cudaGetSymbolAddress((void**)&s, d_scratch);

    bf16*  pMeanB = (bf16*)(s + OFF_MEANB);
    bf16*  pAm    = (bf16*)(s + OFF_AM);
    bf16*  pAo    = (bf16*)(s + OFF_AO);
    float* pGm    = s + OFF_GM;
    float* pGo    = s + OFF_GO;
    float* pFm    = s + OFF_FM;
    float* pFo    = s + OFF_FO;
    bf16*  pHmA   = (bf16*)(s + OFF_HMA);
    bf16*  pHmB   = (bf16*)(s + OFF_HMB);
    float* pCm    = s + OFF_CM;
    bf16*  pHoA   = (bf16*)(s + OFF_HOA);
    bf16*  pHoB   = (bf16*)(s + OFF_HOB);
    float* pCo    = s + OFF_CO;
    bf16*  pHms   = (bf16*)(s + OFF_HMS);
    bf16*  pHos   = (bf16*)(s + OFF_HOS);
    float* pOutm  = s + OFF_OUTM;
    float* pOuto  = s + OFF_OUTO;
    bf16*  pWIMin = (bf16*)(s + OFF_WIMIN);
    bf16*  pWIMft = (bf16*)(s + OFF_WIMFT);
    bf16*  pWIOin = (bf16*)(s + OFF_WIOIN);
    bf16*  pWIOft = (bf16*)(s + OFF_WIOFT);
    bf16*  pWHM   = (bf16*)(s + OFF_WHM);
    bf16*  pWHO   = (bf16*)(s + OFF_WHO);
    bf16*  pFCM   = (bf16*)(s + OFF_FCM);
    bf16*  pFCO   = (bf16*)(s + OFF_FCO);
    float* pBM    = s + OFF_BM;
    float* pBO    = s + OFF_BO;

    cudaFuncSetAttribute(gemm_wide, cudaFuncAttributeMaxDynamicSharedMemorySize, DYN_G);

    // launches 1-5 (ncu -s 5 skips these; launch 6 = G_m gemm gets profiled)
    objmean_kernel<<<NB, 256>>>(obj_enc, pMeanB);                                    // 1
    build_Am<<<BT, 256>>>(qzm, x, emd_W, pAm);                                       // 2
    build_Ao<<<BT, 256>>>(qzm, qzo, x, emd_W, pAo);                                  // 3
    reorder_ih<<<GM4, 256>>>(W_ih_m, LDW_M, KIN_M, pWIMin, KAM, pWIMft, NHM);        // 4
    reorder_ih<<<GO4, 256>>>(W_ih_o, LDW_O, KIN_O, pWIOin, KAO, pWIOft, NHO);        // 5

    // 6: THE hot GEMM — G_m = Am @ W_in_m^T (no bias; bias+F folded later)
    gemm_wide<<<dim3(GM4 / 256, BT / 128), 256, DYN_G>>>(
        pAm, KAM, pWIMin, KAM, pGm, GM4, KAM, nullptr);                              // 6
    gemm_wide<<<dim3(GO4 / 256, BT / 128), 256, DYN_G>>>(
        pAo, KAO, pWIOin, KAO, pGo, GO4, KAO, nullptr);                              // 7

    reorder_hh<<<GM4, 256>>>(W_hh_m, pWHM, NHM);
    reorder_hh<<<GO4, 256>>>(W_hh_o, pWHO, NHO);
    reorder_bias<<<(GM4 + 255) / 256, 256>>>(b_m, pBM, NHM);
    reorder_bias<<<(GO4 + 255) / 256, 256>>>(b_o, pBO, NHO);
    f2bf_kernel<<<(1024 * NHM + 255) / 256, 256>>>(fc_m_W, pFCM, 1024 * NHM);
    f2bf_kernel<<<(1024 * NHO + 255) / 256, 256>>>(fc_o_W, pFCO, 1024 * NHO);

    // F = mean @ W_ft^T + bias (bias folded here; added to gates in lstm_step)
    gemm_wide<<<dim3(GM4 / 256, NB / 128), 256, DYN_G>>>(
        pMeanB, ND, pWIMft, ND, pFm, GM4, ND, pBM);
    gemm_wide<<<dim3(GO4 / 256, NB / 128), 256, DYN_G>>>(
        pMeanB, ND, pWIOft, ND, pFo, GO4, ND, pBO);

    zero_state<<<(NB * NHM + 255) / 256, 256>>>(pHmA, pCm, pHoA, pCo);

    for (int t = 0; t < NT; t++) {
        const bf16* hmi = (t & 1) ? pHmB : pHmA;
        bf16*       hmo = (t & 1) ? pHmA : pHmB;
        const bf16* hoi = (t & 1) ? pHoB : pHoA;
        bf16*       hoo = (t & 1) ? pHoA : pHoB;
        lstm_step<<<160, 256>>>(hmi, hmo, pCm, pWHM, pGm, pFm, pHms,
                                hoi, hoo, pCo, pWHO, pGo, pFo, pHos, t);
    }

    gemm_wide<<<dim3((2 * NE) / 256, BT / 128), 256, DYN_G>>>(
        pHms, NHM, pFCM, NHM, pOutm, 2 * NE, NHM, fc_m_b);
    gemm_wide<<<dim3((2 * NE) / 256, BT / 128), 256, DYN_G>>>(
        pHos, NHO, pFCO, NHO, pOuto, 2 * NE, NHO, fc_o_b);

    kl_kernel<<<NB, 256>>>(pOutm, pOuto, qmm, qlm, qmo, qlo, x, out);
}

// round 9
// speedup vs baseline: 1.0714x; 1.0714x over previous
#include <cuda_runtime.h>
#include <cuda_bf16.h>
#include <math.h>

#define NB 512
#define NT 20
#define NOBJ 36
#define ND 2048
#define NEMB 300
#define NE 512
#define NHM 1024
#define NHO 256

constexpr int BT  = NB * NT;          // 10240
constexpr int KAM = 832;
constexpr int KAO = 1344;
constexpr int GM4 = 4 * NHM;          // 4096
constexpr int GO4 = 4 * NHO;          // 1024
constexpr int LDW_M = NE + NEMB + ND;       // 2860
constexpr int LDW_O = 2 * NE + NEMB + ND;   // 3372
constexpr int KIN_M = NE + NEMB;            // 812
constexpr int KIN_O = 2 * NE + NEMB;        // 1324

// ---------------- scratch arena ----------------
constexpr size_t OFF_MEANB = 0;                                      // bf16 NB*ND
constexpr size_t OFF_AM    = OFF_MEANB + (size_t)NB * ND / 2;
constexpr size_t OFF_AO    = OFF_AM    + (size_t)BT * KAM / 2;
constexpr size_t OFF_GM    = OFF_AO    + (size_t)BT * KAO / 2;       // f32
constexpr size_t OFF_GO    = OFF_GM    + (size_t)BT * GM4;
constexpr size_t OFF_FM    = OFF_GO    + (size_t)BT * GO4;
constexpr size_t OFF_FO    = OFF_FM    + (size_t)NB * GM4;
constexpr size_t OFF_HMA   = OFF_FO    + (size_t)NB * GO4;           // bf16
constexpr size_t OFF_HMB   = OFF_HMA   + (size_t)NB * NHM / 2;
constexpr size_t OFF_CM    = OFF_HMB   + (size_t)NB * NHM / 2;       // f32
constexpr size_t OFF_HOA   = OFF_CM    + (size_t)NB * NHM;
constexpr size_t OFF_HOB   = OFF_HOA   + (size_t)NB * NHO / 2;
constexpr size_t OFF_CO    = OFF_HOB   + (size_t)NB * NHO / 2;
constexpr size_t OFF_HMS   = OFF_CO    + (size_t)NB * NHO;           // bf16
constexpr size_t OFF_HOS   = OFF_HMS   + (size_t)BT * NHM / 2;
constexpr size_t OFF_OUTM  = OFF_HOS   + (size_t)BT * NHO / 2;       // f32
constexpr size_t OFF_OUTO  = OFF_OUTM  + (size_t)BT * 2 * NE;
constexpr size_t OFF_WIMIN = OFF_OUTO  + (size_t)BT * 2 * NE;        // bf16
constexpr size_t OFF_WIMFT = OFF_WIMIN + (size_t)GM4 * KAM / 2;
constexpr size_t OFF_WIOIN = OFF_WIMFT + (size_t)GM4 * ND / 2;
constexpr size_t OFF_WIOFT = OFF_WIOIN + (size_t)GO4 * KAO / 2;
constexpr size_t OFF_WHM   = OFF_WIOFT + (size_t)GO4 * ND / 2;
constexpr size_t OFF_WHO   = OFF_WHM   + (size_t)GM4 * NHM / 2;
constexpr size_t OFF_FCM   = OFF_WHO   + (size_t)GO4 * NHO / 2;
constexpr size_t OFF_FCO   = OFF_FCM   + (size_t)1024 * NHM / 2;
constexpr size_t OFF_BM    = OFF_FCO   + (size_t)1024 * NHO / 2;     // f32
constexpr size_t OFF_BO    = OFF_BM    + GM4;
constexpr size_t TOTAL     = OFF_BO    + GO4;

__device__ float d_scratch[TOTAL];
__device__ unsigned d_gbar;

typedef __nv_bfloat16 bf16;

__device__ __forceinline__ uint2 pack4(float4 v) {
    __nv_bfloat162 p0 = __floats2bfloat162_rn(v.x, v.y);
    __nv_bfloat162 p1 = __floats2bfloat162_rn(v.z, v.w);
    uint2 o;
    o.x = *(unsigned*)&p0;
    o.y = *(unsigned*)&p1;
    return o;
}

#define ABLK 40

__device__ __forceinline__ void mma_bf16(float* d, const unsigned* a, const unsigned* b) {
    asm volatile(
        "mma.sync.aligned.m16n8k16.row.col.f32.bf16.bf16.f32 "
        "{%0,%1,%2,%3},{%4,%5,%6,%7},{%8,%9},{%0,%1,%2,%3};"
        : "+f"(d[0]), "+f"(d[1]), "+f"(d[2]), "+f"(d[3])
        : "r"(a[0]), "r"(a[1]), "r"(a[2]), "r"(a[3]), "r"(b[0]), "r"(b[1]));
}

// =====================================================================
// WIDE GEMM: block 128(M) x 256(N), k-tile 32, 8 warps of 64x64.
// =====================================================================
struct __align__(16) SmemBufW {
    unsigned A[4][8 * 2 * ABLK];
    unsigned B[2][32 * 2 * ABLK];
};
#define DYN_G (2 * (int)sizeof(SmemBufW))   // 61440

__device__ __forceinline__ void fill_wide(SmemBufW* buf, int tid,
                                          const uint4* av, const uint4* bv)
{
#pragma unroll
    for (int q = 0; q < 2; q++) {
        int v = tid + q * 256;
        int r = v >> 2, f8 = v & 3;
        int reg = ((r >> 3) & 1) + 2 * (f8 & 1);
        int off = ((r >> 4) * 2 + (f8 >> 1)) * ABLK + 4 * (r & 7);
        *(uint4*)&buf->A[reg][off] = av[q];
    }
#pragma unroll
    for (int q = 0; q < 4; q++) {
        int v = tid + q * 256;
        int r = v >> 2, f8 = v & 3;
        int reg = f8 & 1;
        int off = ((r >> 3) * 2 + (f8 >> 1)) * ABLK + 4 * (r & 7);
        *(uint4*)&buf->B[reg][off] = bv[q];
    }
}

__global__ __launch_bounds__(256, 1) void gemm_wide(
    const bf16* __restrict__ A, int lda,
    const bf16* __restrict__ W, int ldw,
    float* __restrict__ C, int ldc, int K,
    const float* __restrict__ bias)
{
    extern __shared__ SmemBufW sm[];
    const int tid = threadIdx.x;
    const int lane = tid & 31;
    const int w = tid >> 5, wm = w & 1, wn = w >> 1;
    const long bm = (long)blockIdx.y * 128;
    const long bn = (long)blockIdx.x * 256;

    const bf16* Ab = A + bm * (size_t)lda;
    const bf16* Wb = W + bn * (size_t)ldw;

    float acc[4][8][4];
#pragma unroll
    for (int i = 0; i < 4; i++)
#pragma unroll
        for (int j = 0; j < 8; j++)
#pragma unroll
            for (int r = 0; r < 4; r++) acc[i][j][r] = 0.f;

    uint4 av[2], bv[4];
#pragma unroll
    for (int q = 0; q < 2; q++) {
        int v = tid + q * 256;
        int r = v >> 2, f8 = v & 3;
        av[q] = *(const uint4*)(Ab + (size_t)r * lda + 8 * f8);
    }
#pragma unroll
    for (int q = 0; q < 4; q++) {
        int v = tid + q * 256;
        int r = v >> 2, f8 = v & 3;
        bv[q] = *(const uint4*)(Wb + (size_t)r * ldw + 8 * f8);
    }
    fill_wide(&sm[0], tid, av, bv);
    __syncthreads();

    const int KT = K / 32;
    for (int kt = 0; kt < KT; kt++) {
        SmemBufW* b = &sm[kt & 1];
        const bool more = (kt + 1 < KT);
        if (more) {
            int k0 = (kt + 1) * 32;
#pragma unroll
            for (int q = 0; q < 2; q++) {
                int v = tid + q * 256;
                int r = v >> 2, f8 = v & 3;
                av[q] = *(const uint4*)(Ab + (size_t)r * lda + k0 + 8 * f8);
            }
#pragma unroll
            for (int q = 0; q < 4; q++) {
                int v = tid + q * 256;
                int r = v >> 2, f8 = v & 3;
                bv[q] = *(const uint4*)(Wb + (size_t)r * ldw + k0 + 8 * f8);
            }
        }

#pragma unroll
        for (int ik = 0; ik < 2; ik++) {
            unsigned af[4][4], bfr[8][2];
#pragma unroll
            for (int il = 0; il < 4; il++) {
                int off = ((wm * 4 + il) * 2 + ik) * ABLK + lane;
                af[il][0] = b->A[0][off];
                af[il][1] = b->A[1][off];
                af[il][2] = b->A[2][off];
                af[il][3] = b->A[3][off];
            }
#pragma unroll
            for (int jl = 0; jl < 8; jl++) {
                int off = ((wn * 8 + jl) * 2 + ik) * ABLK + lane;
                bfr[jl][0] = b->B[0][off];
                bfr[jl][1] = b->B[1][off];
            }
#pragma unroll
            for (int il = 0; il < 4; il++)
#pragma unroll
                for (int jl = 0; jl < 8; jl++)
                    mma_bf16(acc[il][jl], af[il], bfr[jl]);
        }

        if (more) {
            fill_wide(&sm[(kt + 1) & 1], tid, av, bv);
            __syncthreads();
        }
    }

    const int g = lane >> 2;
    const int cp = (lane & 3) * 2;
#pragma unroll
    for (int jl = 0; jl < 8; jl++) {
        long col = bn + wn * 64 + jl * 8 + cp;
        float b0 = 0.f, b1 = 0.f;
        if (bias) { b0 = bias[col]; b1 = bias[col + 1]; }
#pragma unroll
        for (int il = 0; il < 4; il++) {
            long row = bm + wm * 64 + il * 16 + g;
            *(float2*)(C + row * (long)ldc + col) =
                make_float2(acc[il][jl][0] + b0, acc[il][jl][1] + b1);
            *(float2*)(C + (row + 8) * (long)ldc + col) =
                make_float2(acc[il][jl][2] + b0, acc[il][jl][3] + b1);
        }
    }
}

// =====================================================================
// bf16 HMMA 128x128 core — used by the persistent LSTM kernel
// =====================================================================
struct __align__(16) SmemBuf {
    unsigned A[4][8 * 2 * ABLK];
    unsigned B[2][16 * 2 * ABLK];
};

__device__ __forceinline__ void fill_tiles(SmemBuf* buf, int tid,
                                           const uint4* av, const uint4* bv)
{
#pragma unroll
    for (int q = 0; q < 2; q++) {
        int v = tid + q * 256;
        int r = v >> 2, f8 = v & 3;
        {
            int reg = ((r >> 3) & 1) + 2 * (f8 & 1);
            int off = ((r >> 4) * 2 + (f8 >> 1)) * ABLK + 4 * (r & 7);
            *(uint4*)&buf->A[reg][off] = av[q];
        }
        {
            int reg = f8 & 1;
            int off = ((r >> 3) * 2 + (f8 >> 1)) * ABLK + 4 * (r & 7);
            *(uint4*)&buf->B[reg][off] = bv[q];
        }
    }
}

__device__ __forceinline__ void gemm_core_bf16(
    const bf16* __restrict__ A, int lda,
    const bf16* __restrict__ W, int ldw, int K,
    SmemBuf* sm, int tid, float acc[4][4][4])
{
    const int lane = tid & 31;
    const int w = tid >> 5, wm = w & 1, wn = w >> 1;

#pragma unroll
    for (int i = 0; i < 4; i++)
#pragma unroll
        for (int j = 0; j < 4; j++)
#pragma unroll
            for (int r = 0; r < 4; r++) acc[i][j][r] = 0.f;

    uint4 av[2], bv[2];
#pragma unroll
    for (int q = 0; q < 2; q++) {
        int v = tid + q * 256;
        int r = v >> 2, f8 = v & 3;
        av[q] = *(const uint4*)(A + (size_t)r * lda + 8 * f8);
        bv[q] = *(const uint4*)(W + (size_t)r * ldw + 8 * f8);
    }
    fill_tiles(&sm[0], tid, av, bv);
    __syncthreads();

    const int KT = K / 32;
    for (int kt = 0; kt < KT; kt++) {
        SmemBuf* b = &sm[kt & 1];
        const bool more = (kt + 1 < KT);
        if (more) {
            int k0 = (kt + 1) * 32;
#pragma unroll
            for (int q = 0; q < 2; q++) {
                int v = tid + q * 256;
                int r = v >> 2, f8 = v & 3;
                av[q] = *(const uint4*)(A + (size_t)r * lda + k0 + 8 * f8);
                bv[q] = *(const uint4*)(W + (size_t)r * ldw + k0 + 8 * f8);
            }
        }

#pragma unroll
        for (int ik = 0; ik < 2; ik++) {
            unsigned af[4][4], bfr[4][2];
#pragma unroll
            for (int il = 0; il < 4; il++) {
                int off = ((wm * 4 + il) * 2 + ik) * ABLK + lane;
                af[il][0] = b->A[0][off];
                af[il][1] = b->A[1][off];
                af[il][2] = b->A[2][off];
                af[il][3] = b->A[3][off];
            }
#pragma unroll
            for (int jl = 0; jl < 4; jl++) {
                int off = ((wn * 4 + jl) * 2 + ik) * ABLK + lane;
                bfr[jl][0] = b->B[0][off];
                bfr[jl][1] = b->B[1][off];
            }
#pragma unroll
            for (int il = 0; il < 4; il++)
#pragma unroll
                for (int jl = 0; jl < 4; jl++)
                    mma_bf16(acc[il][jl], af[il], bfr[jl]);
        }

        if (more) {
            fill_tiles(&sm[(kt + 1) & 1], tid, av, bv);
            __syncthreads();
        }
    }
}

// ---------------- fused LSTM cell epilogue ----------------
__device__ __forceinline__ float tfast(float x) {
    float y;
    asm("tanh.approx.f32 %0, %1;" : "=f"(y) : "f"(x));
    return y;
}
__device__ __forceinline__ float sigf(float x) { return 0.5f * tfast(0.5f * x) + 0.5f; }

__device__ __forceinline__ void cell_epi(
    float acc[4][4][4], int tid,
    const float* __restrict__ G, const float* __restrict__ F,
    float* __restrict__ c,
    bf16* __restrict__ hout, bf16* __restrict__ Hseq,
    long bm, int bx, int H, int t)
{
    const int lane = tid & 31;
    const int w = tid >> 5, wm = w & 1, wn = w >> 1;
    const int g = lane >> 2;
    const bool odd = lane & 1;
    const int H4 = 4 * H;

#pragma unroll
    for (int il = 0; il < 4; il++) {
        long row = bm + wm * 64 + il * 16 + g + (odd ? 8 : 0);
#pragma unroll
        for (int jl = 0; jl < 4; jl++) {
            float s0 = odd ? acc[il][jl][0] : acc[il][jl][2];
            float s1 = odd ? acc[il][jl][1] : acc[il][jl][3];
            float r0 = __shfl_xor_sync(0xffffffffu, s0, 1);
            float r1 = __shfl_xor_sync(0xffffffffu, s1, 1);
            float gi, gf, gg, go;
            if (!odd) { gi = acc[il][jl][0]; gf = acc[il][jl][1]; gg = r0; go = r1; }
            else      { gi = r0; gf = r1; gg = acc[il][jl][2]; go = acc[il][jl][3]; }

            int ul = wn * 8 + jl * 2 + ((lane & 2) >> 1);
            size_t goff = (size_t)bx * 128 + ul * 4;
            const float4 G4 = *(const float4*)&G[(row * NT + t) * (size_t)H4 + goff];
            const float4 F4 = *(const float4*)&F[row * (size_t)H4 + goff];
            gi += G4.x + F4.x; gf += G4.y + F4.y;
            gg += G4.z + F4.z; go += G4.w + F4.w;

            int u = bx * 32 + ul;
            size_t si = (size_t)row * H + u;
            float cn = sigf(gf) * c[si] + sigf(gi) * tfast(gg);
            float hn = sigf(go) * tfast(cn);
            c[si] = cn;
            bf16 hb = __float2bfloat16(hn);
            hout[si] = hb;
            Hseq[(row * NT + t) * (size_t)H + u] = hb;
        }
    }
}

// ---------------- persistent recurrence: all 20 steps, 1 launch ----------
__global__ __launch_bounds__(256, 2) void lstm_persist(
    bf16* __restrict__ hmA, bf16* __restrict__ hmB, float* __restrict__ cm,
    const bf16* __restrict__ Whm, const float* __restrict__ Gm,
    const float* __restrict__ Fm, bf16* __restrict__ Hms,
    bf16* __restrict__ hoA, bf16* __restrict__ hoB, float* __restrict__ co,
    const bf16* __restrict__ Who, const float* __restrict__ Go,
    const float* __restrict__ Fo, bf16* __restrict__ Hos)
{
    __shared__ SmemBuf sm[2];
    const int tid = threadIdx.x;
    const int id = blockIdx.x;                 // 0..159, all resident (occ 2)

    for (int t = 0; t < NT; t++) {
        const bf16* hmi = (t & 1) ? hmB : hmA;
        bf16*       hmo = (t & 1) ? hmA : hmB;
        const bf16* hoi = (t & 1) ? hoB : hoA;
        bf16*       hoo = (t & 1) ? hoA : hoB;

        float acc[4][4][4];
        if (id < 128) {
            int bx = id & 31;
            long bm = (long)(id >> 5) * 128;
            gemm_core_bf16(hmi + bm * NHM, NHM, Whm + (size_t)bx * 128 * NHM, NHM,
                           NHM, sm, tid, acc);
            cell_epi(acc, tid, Gm, Fm, cm, hmo, Hms, bm, bx, NHM, t);
        } else {
            int r = id - 128;
            int bx = r & 7;
            long bm = (long)(r >> 3) * 128;
            gemm_core_bf16(hoi + bm * NHO, NHO, Who + (size_t)bx * 128 * NHO, NHO,
                           NHO, sm, tid, acc);
            cell_epi(acc, tid, Go, Fo, co, hoo, Hos, bm, bx, NHO, t);
        }

        // software grid barrier (monotonic counter, sense-free)
        __syncthreads();
        if (tid == 0) {
            __threadfence();
            atomicAdd(&d_gbar, 1u);
            unsigned tgt = 160u * (unsigned)(t + 1);
            while (*((volatile unsigned*)&d_gbar) < tgt) { }
            __threadfence();
        }
        __syncthreads();
    }
}

// ---------------- setup kernels (vectorized) ----------------
__global__ void objmean_kernel(const float* __restrict__ obj, bf16* __restrict__ meanb)
{
    int b = blockIdx.x;
    int tid = threadIdx.x;
    int w = tid >> 5, lane = tid & 31;
    __shared__ float mk[NOBJ];

    for (int n = w; n < NOBJ; n += 8) {
        const float* p = obj + ((size_t)b * NOBJ + n) * ND;
        float s = 0.f;
        for (int d = lane; d < ND; d += 32) s += fabsf(p[d]);
        for (int o = 16; o; o >>= 1) s += __shfl_down_sync(0xffffffffu, s, o);
        if (lane == 0) mk[n] = s > 0.f ? 1.f : 0.f;
    }
    __syncthreads();
    float cnt = 0.f;
#pragma unroll
    for (int n = 0; n < NOBJ; n++) cnt += mk[n];
    float inv = 1.f / fmaxf(cnt, 1e-9f);

    const float* ob = obj + (size_t)b * NOBJ * ND;
    for (int d = tid; d < ND; d += 256) {
        float acc = 0.f;
#pragma unroll 4
        for (int n = 0; n < NOBJ; n++) acc += ob[(size_t)n * ND + d] * mk[n];
        meanb[(size_t)b * ND + d] = __float2bfloat16(acc * inv);
    }
}

__global__ void build_Am(const float* __restrict__ qzm, const int* __restrict__ x,
                         const float* __restrict__ emb, bf16* __restrict__ Am)
{
    int r = blockIdx.x;
    int t = r % NT, b = r / NT;
    uint2* out = (uint2*)(Am + (size_t)r * KAM);
    const float* z = qzm + ((size_t)b * NT + (t - 1)) * NE;
    const float* e = emb + (size_t)x[r] * NEMB;
    for (int c4 = threadIdx.x; c4 < KAM / 4; c4 += blockDim.x) {
        int c = c4 * 4;
        float4 v = make_float4(0.f, 0.f, 0.f, 0.f);
        if (c < NE) { if (t > 0) v = *(const float4*)(z + c); }
        else if (c < NE + NEMB) v = *(const float4*)(e + (c - NE));
        out[c4] = pack4(v);
    }
}

__global__ void build_Ao(const float* __restrict__ qzm, const float* __restrict__ qzo,
                         const int* __restrict__ x, const float* __restrict__ emb,
                         bf16* __restrict__ Ao)
{
    int r = blockIdx.x;
    int t = r % NT, b = r / NT;
    uint2* out = (uint2*)(Ao + (size_t)r * KAO);
    const float* zc = qzm + ((size_t)b * NT + t) * NE;
    const float* zp = qzo + ((size_t)b * NT + (t - 1)) * NE;
    const float* e  = emb + (size_t)x[r] * NEMB;
    for (int c4 = threadIdx.x; c4 < KAO / 4; c4 += blockDim.x) {
        int c = c4 * 4;
        float4 v = make_float4(0.f, 0.f, 0.f, 0.f);
        if (c < NE)                 v = *(const float4*)(zc + c);
        else if (c < 2 * NE)        { if (t > 0) v = *(const float4*)(zp + (c - NE)); }
        else if (c < 2 * NE + NEMB) v = *(const float4*)(e + (c - 2 * NE));
        out[c4] = pack4(v);
    }
}

__global__ void reorder_ih(const float* __restrict__ src, int ldsrc, int kin,
                           bf16* __restrict__ din, int ldin,
                           bf16* __restrict__ dft, int H)
{
    int r = blockIdx.x;
    int u = r >> 2, g = r & 3;
    const float* s = src + (size_t)(g * H + u) * ldsrc;
    uint2* a = (uint2*)(din + (size_t)r * ldin);
    uint2* b = (uint2*)(dft + (size_t)r * ND);
    for (int c4 = threadIdx.x; c4 < ldin / 4; c4 += blockDim.x) {
        int c = c4 * 4;
        float4 v = (c < kin) ? *(const float4*)(s + c) : make_float4(0.f, 0.f, 0.f, 0.f);
        a[c4] = pack4(v);
    }
    for (int c4 = threadIdx.x; c4 < ND / 4; c4 += blockDim.x)
        b[c4] = pack4(*(const float4*)(s + kin + c4 * 4));
}

__global__ void reorder_hh(const float* __restrict__ src, bf16* __restrict__ dst, int H)
{
    int r = blockIdx.x;
    int u = r >> 2, g = r & 3;
    const float* s = src + (size_t)(g * H + u) * H;
    uint2* d = (uint2*)(dst + (size_t)r * H);
    for (int c4 = threadIdx.x; c4 < H / 4; c4 += blockDim.x)
        d[c4] = pack4(*(const float4*)(s + c4 * 4));
}

__global__ void reorder_bias(const float* __restrict__ src, float* __restrict__ dst, int H)
{
    int r = blockIdx.x * blockDim.x + threadIdx.x;
    if (r < 4 * H) { int u = r >> 2, g = r & 3; dst[r] = src[g * H + u]; }
}

__global__ void f2bf_kernel(const float* __restrict__ s, bf16* __restrict__ d, int n)
{
    int i = blockIdx.x * blockDim.x + threadIdx.x;
    if (i * 4 < n) d[i] = (bf16)0;   // placeholder avoided; real work below
}

__global__ void f2bf4_kernel(const float* __restrict__ s, bf16* __restrict__ d, int n4)
{
    int i = blockIdx.x * blockDim.x + threadIdx.x;
    if (i < n4) ((uint2*)d)[i] = pack4(((const float4*)s)[i]);
}

__global__ void zero_state(bf16* hm, float* cm, bf16* ho, float* co)
{
    int idx = blockIdx.x * blockDim.x + threadIdx.x;
    if (idx == 0) d_gbar = 0u;
    if (idx < NB * NHM) { hm[idx] = __float2bfloat16(0.f); cm[idx] = 0.f; }
    if (idx < NB * NHO) { ho[idx] = __float2bfloat16(0.f); co[idx] = 0.f; }
}

__device__ __forceinline__ float kl1(float pm, float pl, float qm, float ql)
{
    float dm = qm - pm;
    return 0.5f * (pl - ql) + (expf(ql) + dm * dm) / (2.f * expf(pl)) - 0.5f;
}

__global__ void kl_kernel(const float* __restrict__ outm, const float* __restrict__ outo,
                          const float* __restrict__ qmm, const float* __restrict__ qlm,
                          const float* __restrict__ qmo, const float* __restrict__ qlo,
                          const int* __restrict__ x, float* __restrict__ out)
{
    int b = blockIdx.x;
    float acc = 0.f;
    const int NV = NT * (NE / 4);
    for (int i4 = threadIdx.x; i4 < NV; i4 += blockDim.x) {
        int t = i4 / (NE / 4);
        int e4 = i4 - t * (NE / 4);
        int tok = x[b * NT + t];
        if (tok == 0 || tok == 2) continue;
        size_t ro = (size_t)b * NT + t;
        size_t po = ro * (2 * NE) + e4 * 4;
        size_t qo = ro * NE + e4 * 4;
        float4 pm = *(const float4*)&outm[po];
        float4 pl = *(const float4*)&outm[po + NE];
        float4 qm = *(const float4*)&qmm[qo];
        float4 ql = *(const float4*)&qlm[qo];
        acc += kl1(pm.x, pl.x, qm.x, ql.x) + kl1(pm.y, pl.y, qm.y, ql.y)
             + kl1(pm.z, pl.z, qm.z, ql.z) + kl1(pm.w, pl.w, qm.w, ql.w);
        pm = *(const float4*)&outo[po];
        pl = *(const float4*)&outo[po + NE];
        qm = *(const float4*)&qmo[qo];
        ql = *(const float4*)&qlo[qo];
        acc += kl1(pm.x, pl.x, qm.x, ql.x) + kl1(pm.y, pl.y, qm.y, ql.y)
             + kl1(pm.z, pl.z, qm.z, ql.z) + kl1(pm.w, pl.w, qm.w, ql.w);
    }
    __shared__ float sm[256];
    sm[threadIdx.x] = acc;
    __syncthreads();
    for (int s = 128; s; s >>= 1) {
        if (threadIdx.x < s) sm[threadIdx.x] += sm[threadIdx.x + s];
        __syncthreads();
    }
    if (threadIdx.x == 0) out[b] = sm[0];
}

// ---------------- host ----------------
extern "C" void kernel_launch(void* const* d_in, const int* in_sizes, int n_in,
                              void* d_out, int out_size)
{
    const float* obj_enc = (const float*)d_in[0];
    const int*   x       = (const int*)  d_in[1];
    const float* qmm     = (const float*)d_in[2];
    const float* qlm     = (const float*)d_in[3];
    const float* qzm     = (const float*)d_in[4];
    const float* qmo     = (const float*)d_in[5];
    const float* qlo     = (const float*)d_in[6];
    const float* qzo     = (const float*)d_in[7];
    const float* emd_W   = (const float*)d_in[8];
    const float* W_ih_m  = (const float*)d_in[9];
    const float* W_hh_m  = (const float*)d_in[10];
    const float* b_m     = (const float*)d_in[11];
    const float* W_ih_o  = (const float*)d_in[12];
    const float* W_hh_o  = (const float*)d_in[13];
    const float* b_o     = (const float*)d_in[14];
    const float* fc_m_W  = (const float*)d_in[15];
    const float* fc_m_b  = (const float*)d_in[16];
    const float* fc_o_W  = (const float*)d_in[17];
    const float* fc_o_b  = (const float*)d_in[18];
    float* out = (float*)d_out;

    float* s = nullptr;
    cudaGetSymbolAddress((void**)&s, d_scratch);

    bf16*  pMeanB = (bf16*)(s + OFF_MEANB);
    bf16*  pAm    = (bf16*)(s + OFF_AM);
    bf16*  pAo    = (bf16*)(s + OFF_AO);
    float* pGm    = s + OFF_GM;
    float* pGo    = s + OFF_GO;
    float* pFm    = s + OFF_FM;
    float* pFo    = s + OFF_FO;
    bf16*  pHmA   = (bf16*)(s + OFF_HMA);
    bf16*  pHmB   = (bf16*)(s + OFF_HMB);
    float* pCm    = s + OFF_CM;
    bf16*  pHoA   = (bf16*)(s + OFF_HOA);
    bf16*  pHoB   = (bf16*)(s + OFF_HOB);
    float* pCo    = s + OFF_CO;
    bf16*  pHms   = (bf16*)(s + OFF_HMS);
    bf16*  pHos   = (bf16*)(s + OFF_HOS);
    float* pOutm  = s + OFF_OUTM;
    float* pOuto  = s + OFF_OUTO;
    bf16*  pWIMin = (bf16*)(s + OFF_WIMIN);
    bf16*  pWIMft = (bf16*)(s + OFF_WIMFT);
    bf16*  pWIOin = (bf16*)(s + OFF_WIOIN);
    bf16*  pWIOft = (bf16*)(s + OFF_WIOFT);
    bf16*  pWHM   = (bf16*)(s + OFF_WHM);
    bf16*  pWHO   = (bf16*)(s + OFF_WHO);
    bf16*  pFCM   = (bf16*)(s + OFF_FCM);
    bf16*  pFCO   = (bf16*)(s + OFF_FCO);
    float* pBM    = s + OFF_BM;
    float* pBO    = s + OFF_BO;

    cudaFuncSetAttribute(gemm_wide, cudaFuncAttributeMaxDynamicSharedMemorySize, DYN_G);

    // Launches 1-3 feed launch 4; ncu's profile window lands on OUR #4,
    // so #4 is the hot G_m GEMM this time.
    build_Am<<<BT, 256>>>(qzm, x, emd_W, pAm);                                   // 1
    build_Ao<<<BT, 256>>>(qzm, qzo, x, emd_W, pAo);                              // 2
    reorder_ih<<<GM4, 256>>>(W_ih_m, LDW_M, KIN_M, pWIMin, KAM, pWIMft, NHM);    // 3
    gemm_wide<<<dim3(GM4 / 256, BT / 128), 256, DYN_G>>>(
        pAm, KAM, pWIMin, KAM, pGm, GM4, KAM, nullptr);                          // 4 (profiled)

    reorder_ih<<<GO4, 256>>>(W_ih_o, LDW_O, KIN_O, pWIOin, KAO, pWIOft, NHO);
    gemm_wide<<<dim3(GO4 / 256, BT / 128), 256, DYN_G>>>(
        pAo, KAO, pWIOin, KAO, pGo, GO4, KAO, nullptr);

    objmean_kernel<<<NB, 256>>>(obj_enc, pMeanB);
    reorder_hh<<<GM4, 256>>>(W_hh_m, pWHM, NHM);
    reorder_hh<<<GO4, 256>>>(W_hh_o, pWHO, NHO);
    reorder_bias<<<(GM4 + 255) / 256, 256>>>(b_m, pBM, NHM);
    reorder_bias<<<(GO4 + 255) / 256, 256>>>(b_o, pBO, NHO);
    f2bf4_kernel<<<(1024 * NHM / 4 + 255) / 256, 256>>>(fc_m_W, pFCM, 1024 * NHM / 4);
    f2bf4_kernel<<<(1024 * NHO / 4 + 255) / 256, 256>>>(fc_o_W, pFCO, 1024 * NHO / 4);

    // F = mean @ W_ft^T + bias (added to gates inside lstm_persist)
    gemm_wide<<<dim3(GM4 / 256, NB / 128), 256, DYN_G>>>(
        pMeanB, ND, pWIMft, ND, pFm, GM4, ND, pBM);
    gemm_wide<<<dim3(GO4 / 256, NB / 128), 256, DYN_G>>>(
        pMeanB, ND, pWIOft, ND, pFo, GO4, ND, pBO);

    zero_state<<<(NB * NHM + 255) / 256, 256>>>(pHmA, pCm, pHoA, pCo);

    // all 20 timesteps in one persistent launch
    lstm_persist<<<160, 256>>>(pHmA, pHmB, pCm, pWHM, pGm, pFm, pHms,
                               pHoA, pHoB, pCo, pWHO, pGo, pFo, pHos);

    gemm_wide<<<dim3((2 * NE) / 256, BT / 128), 256, DYN_G>>>(
        pHms, NHM, pFCM, NHM, pOutm, 2 * NE, NHM, fc_m_b);
    gemm_wide<<<dim3((2 * NE) / 256, BT / 128), 256, DYN_G>>>(
        pHos, NHO, pFCO, NHO, pOuto, 2 * NE, NHO, fc_o_b);

    kl_kernel<<<NB, 256>>>(pOutm, pOuto, qmm, qlm, qmo, qlo, x, out);
}